// round 11
// baseline (speedup 1.0000x reference)
#include <cuda_runtime.h>
#include <cuda_fp16.h>
#include <cstdint>

// ---------------------------------------------------------------------------
// Problem constants
constexpr int B_   = 4;
constexpr int G_   = 8;
constexpr int NH_  = 8;
constexpr int DIM_ = 256;    // HID / G
constexpr int S_   = 4096;
constexpr int SPAD = 4104;   // padded K/V time pitch (S_+1, rounded to 8)
constexpr int HID_ = 2048;
constexpr int KP   = 256;    // K (plain fp16, single term)

// ---------------------------------------------------------------------------
// Scratch (device globals; allocation is forbidden) — fp16
__device__ __half g_Q[(size_t)B_ * G_ * DIM_ * S_];    // (bg, c, s)
__device__ __half g_K[(size_t)B_ * G_ * DIM_ * SPAD];  // (bg, c, t) t in [0,4096]
__device__ __half g_V[(size_t)B_ * G_ * DIM_ * SPAD];

__device__ __half g_Bx[(size_t)32 * 256 * S_];
__device__ __half g_Bo[(size_t)32 * 256 * S_];
__device__ __half g_Aq[(size_t)G_ * 768 * KP];  // w_qkv fp16 [g][o][c]
__device__ __half g_Ap[(size_t)G_ * 256 * KP];  // w_pred fp16

// ---------------------------------------------------------------------------
__device__ __forceinline__ uint32_t smem_u32(const void* p) {
    uint32_t a;
    asm("{ .reg .u64 t; cvta.to.shared.u64 t, %1; cvt.u32.u64 %0, t; }" : "=r"(a) : "l"(p));
    return a;
}
__device__ __forceinline__ void cp_async16(uint32_t dst, const void* src) {
    asm volatile("cp.async.cg.shared.global [%0], [%1], 16;" :: "r"(dst), "l"(src));
}
__device__ __forceinline__ void ldmatrix_x4(uint32_t* r, uint32_t addr) {
    asm volatile("ldmatrix.sync.aligned.m8n8.x4.shared.b16 {%0,%1,%2,%3}, [%4];"
                 : "=r"(r[0]), "=r"(r[1]), "=r"(r[2]), "=r"(r[3]) : "r"(addr));
}
__device__ __forceinline__ void ldmatrix_x4_trans(uint32_t* r, uint32_t addr) {
    asm volatile("ldmatrix.sync.aligned.m8n8.x4.trans.shared.b16 {%0,%1,%2,%3}, [%4];"
                 : "=r"(r[0]), "=r"(r[1]), "=r"(r[2]), "=r"(r[3]) : "r"(addr));
}
__device__ __forceinline__ void mma16816(float* c, const uint32_t* a, uint32_t b0, uint32_t b1) {
    asm volatile(
        "mma.sync.aligned.m16n8k16.row.col.f32.f16.f16.f32 "
        "{%0,%1,%2,%3}, {%4,%5,%6,%7}, {%8,%9}, {%0,%1,%2,%3};"
        : "+f"(c[0]), "+f"(c[1]), "+f"(c[2]), "+f"(c[3])
        : "r"(a[0]), "r"(a[1]), "r"(a[2]), "r"(a[3]), "r"(b0), "r"(b1));
}

// ---------------------------------------------------------------------------
__global__ void convert_w(const float* __restrict__ w, __half* __restrict__ A,
                          int total) {
    int i = blockIdx.x * 256 + threadIdx.x;
    if (i >= total) return;
    A[i] = __float2half(w[i]);
}

// x fp32 -> g_Bx fp16 (elementwise)
__global__ __launch_bounds__(256)
void convert_x(const float* __restrict__ x, __half* __restrict__ dst) {
    int i = blockIdx.x * 256 + threadIdx.x;  // over 32*256*1024 float4 slots
    size_t base = (size_t)i << 2;
    float4 v = *reinterpret_cast<const float4*>(x + base);
    __half2 h0, h1;
    h0.x = __float2half(v.x); h0.y = __float2half(v.y);
    h1.x = __float2half(v.z); h1.y = __float2half(v.w);
    __half2* dh = reinterpret_cast<__half2*>(dst + base);
    dh[0] = h0; dh[1] = h1;
}

// ---------------------------------------------------------------------------
// mma.sync GEMM: D[128 o x 128 t] = A[o][k 256] . B[t][k 256]
// 4 warps, warp tile 64x64, BK=32, 4-stage cp.async, 1 barrier/chunk.
// ---------------------------------------------------------------------------
constexpr int NCH = 8;

__global__ __launch_bounds__(128, 2)
void gemm_mma(const __half* __restrict__ Aall,
              const __half* __restrict__ Ball,
              const float* __restrict__ bias,
              int Mtot, int mode, float* __restrict__ out) {
    extern __shared__ __align__(1024) char sbuf[];  // 4 * 16384
    const int tid  = threadIdx.x;
    const int lane = tid & 31;
    const int wid  = tid >> 5;
    const int wm   = wid & 1;
    const int wn   = wid >> 1;
    const int bg = blockIdx.z, g = bg & 7;
    const int o0 = blockIdx.y * 128, t0 = blockIdx.x * 128;

    const uint32_t sbase = smem_u32(sbuf);
    const __half* A  = Aall + ((size_t)g * Mtot + o0) * KP;
    const __half* Bp = Ball + (size_t)bg * 256 * S_;

    auto load_stage = [&](int ch, int st) {
        uint32_t sA = sbase + st * 16384;
        uint32_t sB = sA + 8192;
        const char* a8 = (const char*)A + (size_t)ch * 64;
        const char* b8 = (const char*)(Bp + ((size_t)ch * 32) * S_ + t0);
#pragma unroll
        for (int i = 0; i < 4; i++) {
            int id = tid + i * 128;
            int ra = id >> 2, ca = id & 3;
            uint32_t offA = ra * 64 + ((ca ^ ((ra >> 1) & 3)) << 4);
            cp_async16(sA + offA, a8 + (size_t)ra * (KP * 2) + ca * 16);
            int rb = id >> 4, cb = id & 15;
            uint32_t offB = rb * 256 + ((cb ^ (rb & 7)) << 4);
            cp_async16(sB + offB, b8 + (size_t)rb * (S_ * 2) + cb * 16);
        }
    };

    float acc[4][8][4];
#pragma unroll
    for (int mi = 0; mi < 4; mi++)
#pragma unroll
        for (int nj = 0; nj < 8; nj++)
#pragma unroll
            for (int q = 0; q < 4; q++) acc[mi][nj][q] = 0.f;

    load_stage(0, 0);
    asm volatile("cp.async.commit_group;" ::: "memory");
    load_stage(1, 1);
    asm volatile("cp.async.commit_group;" ::: "memory");
    load_stage(2, 2);
    asm volatile("cp.async.commit_group;" ::: "memory");

    const int gsel = lane >> 3;
    const int rin  = lane & 7;
    const int bl   = lane & 15;
    const int bh   = lane >> 4;

    for (int ch = 0; ch < NCH; ch++) {
        if (ch < NCH - 3) asm volatile("cp.async.wait_group 2;" ::: "memory");
        else              asm volatile("cp.async.wait_group 0;" ::: "memory");
        __syncthreads();
        if (ch + 3 < NCH) {
            load_stage(ch + 3, (ch + 3) & 3);
            asm volatile("cp.async.commit_group;" ::: "memory");
        }
        uint32_t sA = sbase + (ch & 3) * 16384;
        uint32_t sB = sA + 8192;
#pragma unroll
        for (int kk = 0; kk < 2; kk++) {
            uint32_t afr[4][4];
#pragma unroll
            for (int mi = 0; mi < 4; mi++) {
                int row   = wm * 64 + mi * 16 + (gsel & 1) * 8 + rin;
                int chunk = kk * 2 + (gsel >> 1);
                uint32_t addr = sA + row * 64 + ((chunk ^ ((row >> 1) & 3)) << 4);
                ldmatrix_x4(afr[mi], addr);
            }
            uint32_t bfr[4][4];
#pragma unroll
            for (int nt = 0; nt < 4; nt++) {
                int krow  = kk * 16 + bl;
                int chunk = wn * 8 + nt * 2 + bh;
                uint32_t addr = sB + krow * 256 + ((chunk ^ (krow & 7)) << 4);
                ldmatrix_x4_trans(bfr[nt], addr);
            }
#pragma unroll
            for (int mi = 0; mi < 4; mi++)
#pragma unroll
                for (int nj = 0; nj < 8; nj++)
                    mma16816(acc[mi][nj], afr[mi],
                             bfr[nj >> 1][(nj & 1) * 2], bfr[nj >> 1][(nj & 1) * 2 + 1]);
        }
    }

    // Epilogue
#pragma unroll
    for (int mi = 0; mi < 4; mi++) {
#pragma unroll
        for (int half = 0; half < 2; half++) {
            int o = o0 + wm * 64 + mi * 16 + half * 8 + (lane >> 2);
            if (mode == 0) {
                int c2 = o / 3;
                int j  = o - c2 * 3;
                float bv = bias[g * 768 + o];
                __half* dst;
                if (j == 0)      dst = g_Q + ((size_t)bg * DIM_ + c2) * S_;
                else if (j == 1) dst = g_K + ((size_t)bg * DIM_ + c2) * SPAD;
                else             dst = g_V + ((size_t)bg * DIM_ + c2) * SPAD;
                dst += t0 + wn * 64 + (lane & 3) * 2;
#pragma unroll
                for (int nj = 0; nj < 8; nj++) {
                    __half2 hv;
                    hv.x = __float2half(acc[mi][nj][half * 2 + 0] + bv);
                    hv.y = __float2half(acc[mi][nj][half * 2 + 1] + bv);
                    *reinterpret_cast<__half2*>(dst + nj * 8) = hv;
                }
            } else {
                float bv = bias[g * 256 + o];
                float* dst = out + ((size_t)bg * 256 + o) * S_
                           + t0 + wn * 64 + (lane & 3) * 2;
#pragma unroll
                for (int nj = 0; nj < 8; nj++) {
                    float2 v;
                    v.x = acc[mi][nj][half * 2 + 0] + bv;
                    v.y = acc[mi][nj][half * 2 + 1] + bv;
                    *reinterpret_cast<float2*>(dst + nj * 8) = v;
                }
            }
        }
    }
}

// ---------------------------------------------------------------------------
// Fill K/V pad column t=4096 with bias
// ---------------------------------------------------------------------------
__global__ void fill_pad(const float* __restrict__ b_qkv) {
    int i = blockIdx.x * 256 + threadIdx.x;  // 32*256
    int bg = i >> 8, c2 = i & 255, g = bg & 7;
    g_K[((size_t)bg * DIM_ + c2) * SPAD + S_] = __float2half(b_qkv[g * 768 + c2 * 3 + 1]);
    g_V[((size_t)bg * DIM_ + c2) * SPAD + S_] = __float2half(b_qkv[g * 768 + c2 * 3 + 2]);
}

// ---------------------------------------------------------------------------
// Attention: thread = (b, n, s, ty) where ty=0..3 owns g in {2ty, 2ty+1}.
// g never reduces across threads (normalization sums over e only).
// Block (128,4)=512 thr: 4x shorter dependent chain per thread vs 1-thread-8g.
// ---------------------------------------------------------------------------
__global__ __launch_bounds__(512, 1)
void attn_kernel(float* __restrict__ attn_out) {
    const int s  = blockIdx.x * 128 + threadIdx.x;
    const int ty = threadIdx.y;      // 0..3
    const int g0 = ty * 2;
    const int n  = blockIdx.y;
    const int b  = blockIdx.z;

    float sc[2][16];
#pragma unroll
    for (int gi = 0; gi < 2; gi++)
#pragma unroll
        for (int e = 0; e < 16; e++) sc[gi][e] = 0.f;

    const size_t qbase = ((size_t)b * G_ * DIM_ + g0 * DIM_ + n * 32) * S_ + s;
    const size_t kbase = ((size_t)b * G_ * DIM_ + n * 32) * SPAD + s;

#pragma unroll 4
    for (int d = 0; d < 32; d++) {
        float qv[2], kv[16];
        qv[0] = __half2float(g_Q[qbase + (size_t)d * S_]);
        qv[1] = __half2float(g_Q[qbase + (size_t)(DIM_ + d) * S_]);
#pragma unroll
        for (int e = 0; e < 8; e++) {
            size_t ko = kbase + (size_t)(e * DIM_ + d) * SPAD;
            kv[e]     = __half2float(g_K[ko]);
            kv[e + 8] = __half2float(g_K[ko + 1]);
        }
#pragma unroll
        for (int gi = 0; gi < 2; gi++)
#pragma unroll
            for (int e = 0; e < 16; e++) sc[gi][e] += qv[gi] * kv[e];
    }

    const float scale = 0.17677669529663687f;  // 1/sqrt(32)
    const size_t abase = (size_t)(b * NH_ + n) * 128 * S_ + s;
#pragma unroll
    for (int gi = 0; gi < 2; gi++) {
        float rs = 1e-9f;
#pragma unroll
        for (int e = 0; e < 16; e++) {
            float z = 1.f / (1.f + __expf(-sc[gi][e] * scale));
            sc[gi][e] = z;
            rs += z;
        }
        float inv = 1.f / rs;
#pragma unroll
        for (int e = 0; e < 16; e++) {
            sc[gi][e] *= inv;
            attn_out[abase + (size_t)((g0 + gi) * 16 + e) * S_] = sc[gi][e];
        }
    }

    // AV + fp16 write into g_Bo[bg][c], c = n*32+d
#pragma unroll 2
    for (int d = 0; d < 32; d++) {
        float vv[16];
#pragma unroll
        for (int e = 0; e < 8; e++) {
            size_t vo = kbase + (size_t)(e * DIM_ + d) * SPAD;
            vv[e]     = __half2float(g_V[vo]);
            vv[e + 8] = __half2float(g_V[vo + 1]);
        }
#pragma unroll
        for (int gi = 0; gi < 2; gi++) {
            float a = 0.f;
#pragma unroll
            for (int e = 0; e < 16; e++) a += sc[gi][e] * vv[e];
            g_Bo[((size_t)(b * 8 + g0 + gi) * 256 + n * 32 + d) * S_ + s] = __float2half(a);
        }
    }
}

// ---------------------------------------------------------------------------
// Serial launcher (single legacy stream; no streams/events — allocation-safe)
// ---------------------------------------------------------------------------
extern "C" void kernel_launch(void* const* d_in, const int* in_sizes, int n_in,
                              void* d_out, int out_size) {
    const float* x      = (const float*)d_in[0];
    const float* w_qkv  = (const float*)d_in[1];
    const float* b_qkv  = (const float*)d_in[2];
    const float* w_pred = (const float*)d_in[3];
    const float* b_pred = (const float*)d_in[4];

    float* pred = (float*)d_out;
    float* attn = pred + (size_t)B_ * HID_ * S_;

    void *pAq, *pAp, *pBx, *pBo;
    cudaGetSymbolAddress(&pAq, g_Aq);
    cudaGetSymbolAddress(&pAp, g_Ap);
    cudaGetSymbolAddress(&pBx, g_Bx);
    cudaGetSymbolAddress(&pBo, g_Bo);

    cudaFuncSetAttribute(gemm_mma, cudaFuncAttributeMaxDynamicSharedMemorySize, 65536);

    convert_w<<<(G_ * 768 * 256 + 255) / 256, 256>>>(w_qkv, (__half*)pAq, G_ * 768 * 256);
    convert_w<<<(G_ * 256 * 256 + 255) / 256, 256>>>(w_pred, (__half*)pAp, G_ * 256 * 256);
    convert_x<<<32 * 256 * 1024 / 256, 256>>>(x, (__half*)pBx);
    fill_pad<<<32, 256>>>(b_qkv);

    gemm_mma<<<dim3(32, 6, 32), 128, 65536>>>((const __half*)pAq,
                                              (const __half*)pBx,
                                              b_qkv, 768, 0, nullptr);

    attn_kernel<<<dim3(S_ / 128, NH_, B_), dim3(128, 4)>>>(attn);

    gemm_mma<<<dim3(32, 2, 32), 128, 65536>>>((const __half*)pAp,
                                              (const __half*)pBo,
                                              b_pred, 256, 1, pred);
}